// round 13
// baseline (speedup 1.0000x reference)
#include <cuda_runtime.h>
#include <cuda_bf16.h>
#include <math.h>
#include <stdint.h>

#define NLM  25
#define CC   128
#define NB   16384
#define RB   16
#define RA   15
#define GRES 240
#define PI_D 3.14159265358979323846264338327950288
#define MSTRIDE 700            // 175 float4 per M row, 16B-aligned rows
#define OUTW 3200
#define BUFSTRIDE 133          // reorder smem row stride (bank-spread)
typedef unsigned long long ull;

// ---------------- device globals ----------------
__device__ float  d_T2[NLM * NLM * NLM];                 // k-major: [k][e], e=i*25+j (w2 folded)
__device__ float  d_M[(size_t)NB * MSTRIDE];             // per-b M, col = i*28+j
__device__ __nv_bfloat16 g_fh[(size_t)NLM * NB * CC];    // feat hi  [i][b][c]
__device__ __nv_bfloat16 g_fl[(size_t)NLM * NB * CC];    // feat lo
__device__ float  g_o[(size_t)NB * OUTW];                // GEMM result [b][i*128+a]
__device__ unsigned short d_map[OUTW];                   // out col -> i*BUFSTRIDE+a (padded)

__constant__ int c_lidx[NLM] = {0, 1,1,1, 2,2,2,2,2, 3,3,3,3,3,3,3, 4,4,4,4,4,4,4,4,4};

__constant__ double c_glx[8] = {
    0.09501250983763744, 0.28160355077925891, 0.45801677765722739, 0.61787624440264375,
    0.75540440835500303, 0.86563120238783174, 0.94457502307323258, 0.98940093499164993 };
__constant__ double c_glw[8] = {
    0.18945061045506850, 0.18260341504492359, 0.16915651939500254, 0.14959598881657673,
    0.12462897125553387, 0.09515851168249278, 0.06225352393864789, 0.02715245941175409 };

// ---------------- helpers ----------------
__device__ __forceinline__ ull pk(float lo, float hi) {
    ull r; asm("mov.b64 %0, {%1, %2};" : "=l"(r) : "f"(lo), "f"(hi)); return r;
}
__device__ __forceinline__ void upk(ull v, float &lo, float &hi) {
    asm("mov.b64 {%0, %1}, %2;" : "=f"(lo), "=f"(hi) : "l"(v));
}
__device__ __forceinline__ void fma2(ull &d, ull a, ull b) {
    asm("fma.rn.f32x2 %0, %1, %2, %0;" : "+l"(d) : "l"(a), "l"(b));
}
__device__ __forceinline__ uint32_t smem_u32(const void* p) {
    uint32_t a;
    asm("{ .reg .u64 t; cvta.to.shared.u64 t, %1; cvt.u32.u64 %0, t; }" : "=r"(a) : "l"(p));
    return a;
}
__device__ __forceinline__ void cpa16(uint32_t dst, const void* src) {
    asm volatile("cp.async.cg.shared.global [%0], [%1], 16;" :: "r"(dst), "l"(src) : "memory");
}
#define CP_COMMIT() asm volatile("cp.async.commit_group;" ::: "memory")
#define CP_WAIT(n)  asm volatile("cp.async.wait_group %0;" :: "n"(n) : "memory")

__device__ __forceinline__ void ldsm4(uint32_t* r, uint32_t addr) {
    asm volatile("ldmatrix.sync.aligned.m8n8.x4.shared.b16 {%0,%1,%2,%3}, [%4];"
        : "=r"(r[0]), "=r"(r[1]), "=r"(r[2]), "=r"(r[3]) : "r"(addr));
}
__device__ __forceinline__ void mma16816(float* d, const uint32_t* a, const uint32_t* b) {
    asm volatile("mma.sync.aligned.m16n8k16.row.col.f32.bf16.bf16.f32 "
        "{%0,%1,%2,%3}, {%4,%5,%6,%7}, {%8,%9}, {%0,%1,%2,%3};"
        : "+f"(d[0]), "+f"(d[1]), "+f"(d[2]), "+f"(d[3])
        : "r"(a[0]), "r"(a[1]), "r"(a[2]), "r"(a[3]), "r"(b[0]), "r"(b[1]));
}

// ---------------- init: Y + T2[k][e] + out map (single-sync reduction) ----------------
__global__ void __launch_bounds__(256) init_T_kernel(const float* __restrict__ w2) {
    __shared__ float Ys[NLM * GRES];   // 24KB
    __shared__ float redp[8 * NLM];
    int e = blockIdx.x;                // (i,j), 0..624
    int i = e / NLM, j = e % NLM;
    int t = threadIdx.x, wid = t >> 5, lane = t & 31;

    if (e == 0) {                      // build padded out-column permutation map
        for (int c = t; c < OUTW; c += 256) {
            int l = 0;
            while (c >= 128 * (l + 1) * (l + 1)) l++;
            int off = c - 128 * l * l;
            int dd = 2 * l + 1;
            int a = off / dd, mi = off - a * dd;
            d_map[c] = (unsigned short)((l * l + mi) * BUFSTRIDE + a);
        }
    }

    if (t < GRES) {
        int g = t / RA, h = t % RA;
        float xx = (float)((g < 8) ? c_glx[g] : -c_glx[g - 8]);
        float s = sqrtf(fmaxf(0.f, 1.f - xx * xx));
        float P[5][5];
        P[0][0] = 1.f;
        #pragma unroll
        for (int m = 1; m <= 4; m++) P[m][m] = -(2.f * m - 1.f) * s * P[m - 1][m - 1];
        #pragma unroll
        for (int m = 0; m <= 3; m++) P[m + 1][m] = (2.f * m + 1.f) * xx * P[m][m];
        #pragma unroll
        for (int m = 0; m <= 4; m++)
            #pragma unroll
            for (int l = m + 2; l <= 4; l++)
                P[l][m] = ((2.f * l - 1.f) * xx * P[l - 1][m] - (l + m - 1.f) * P[l - 2][m]) / (float)(l - m);
        float alpha = (float)(2.0 * PI_D * (double)h / (double)RA);
        float fact[9]; fact[0] = 1.f;
        #pragma unroll
        for (int q = 1; q < 9; q++) fact[q] = fact[q - 1] * q;
        int ii = 0;
        #pragma unroll
        for (int l = 0; l <= 4; l++)
            for (int mm = -l; mm <= l; mm++) {
                int am = mm < 0 ? -mm : mm;
                float K = sqrtf((2.f * l + 1.f) / (4.f * (float)PI_D) * fact[l - am] / fact[l + am]);
                float y;
                if (mm == 0)      y = K * P[l][0];
                else if (mm > 0)  y = 1.41421356237309515f * K * P[l][am] * cosf(am * alpha);
                else              y = 1.41421356237309515f * K * P[l][am] * sinf(am * alpha);
                Ys[ii * GRES + t] = y;
                ii++;
            }
    }
    __syncthreads();

    float wyy = 0.f;
    if (t < GRES) {
        int g = t / RA;
        float wqv = (float)(c_glw[g & 7] * (2.0 * PI_D / (double)RA));
        wyy = wqv * Ys[i * GRES + t] * Ys[j * GRES + t];
    }
    #pragma unroll
    for (int k = 0; k < NLM; k++) {
        float v = (t < GRES) ? wyy * Ys[k * GRES + t] : 0.f;
        #pragma unroll
        for (int off = 16; off; off >>= 1) v += __shfl_down_sync(0xffffffffu, v, off);
        if (lane == 0) redp[wid * NLM + k] = v;
    }
    __syncthreads();
    if (t < NLM) {
        float s2 = 0.f;
        #pragma unroll
        for (int w = 0; w < 8; w++) s2 += redp[w * NLM + t];
        d_T2[t * (NLM * NLM) + e] = s2 * w2[c_lidx[t]];
    }
}

// ---------------- stage 0: M[b][i,j] = sum_k T2[k][e]*sh[b][k] ----------------
__global__ void __launch_bounds__(640) msolve_kernel(const float* __restrict__ sh) {
    __shared__ __align__(16) ull shp[NLM * 32];   // [k][bpair]
    int t = threadIdx.x;
    int b0 = blockIdx.x * 64;

    for (int q = t; q < NLM * 32; q += 640) {
        int k = q >> 5, bp = q & 31;
        shp[q] = pk(sh[(size_t)(b0 + 2 * bp) * NLM + k], sh[(size_t)(b0 + 2 * bp + 1) * NLM + k]);
    }
    __syncthreads();

    if (t < 625) {
        ull t2p[NLM];
        #pragma unroll
        for (int k = 0; k < NLM; k++) {
            float v = d_T2[k * 625 + t];
            t2p[k] = pk(v, v);
        }
        int col = (t / 25) * 28 + t % 25;
        for (int bq = 0; bq < 16; bq++) {
            ull a0 = 0ULL, a1 = 0ULL;
            #pragma unroll
            for (int k = 0; k < NLM; k++) {
                ulonglong2 sp = *(const ulonglong2*)&shp[k * 32 + 2 * bq];
                fma2(a0, t2p[k], sp.x);
                fma2(a1, t2p[k], sp.y);
            }
            float x0, x1, y0, y1;
            upk(a0, x0, x1); upk(a1, y0, y1);
            size_t r = (size_t)(b0 + 4 * bq) * MSTRIDE + col;
            d_M[r]               = x0;
            d_M[r + MSTRIDE]     = x1;
            d_M[r + 2 * MSTRIDE] = y0;
            d_M[r + 3 * MSTRIDE] = y1;
        }
    }
}

// ---------------- stage 1: feat (bf16 hi/lo), smem-staged wide stores ----------------
__global__ void __launch_bounds__(256) feat_kernel(const float* __restrict__ feature,
                                                   const float* __restrict__ w1) {
    __shared__ float fs[CC * NLM];
    __shared__ __align__(16) float Ms[MSTRIDE];
    __shared__ __align__(16) __nv_bfloat16 sfh[NLM * CC];   // 6.4KB
    __shared__ __align__(16) __nv_bfloat16 sfl[NLM * CC];   // 6.4KB
    int b = blockIdx.x, t = threadIdx.x;

    const float4* f4 = (const float4*)(feature + (size_t)b * (CC * NLM));
    for (int q = t; q < CC * NLM / 4; q += 256) ((float4*)fs)[q] = f4[q];
    const float4* m4 = (const float4*)(d_M + (size_t)b * MSTRIDE);
    for (int q = t; q < MSTRIDE / 4; q += 256) ((float4*)Ms)[q] = m4[q];
    __syncthreads();

    int c = t & 127;
    int half = t >> 7;                 // 0: i2 in [0,13), 1: i2 in [13,25)
    int i2beg = half ? 13 : 0;
    int i2end = half ? 25 : 13;

    float w1r[5];
    #pragma unroll
    for (int l = 0; l < 5; l++) w1r[l] = w1[c * 5 + l];

    float img[NLM];
    {
        int off = 0, j = 0;
        #pragma unroll
        for (int l = 0; l <= 4; l++) {
            int dd = 2 * l + 1;
            #pragma unroll
            for (int m = 0; m < dd; m++) { img[j] = fs[off + c * dd + m] * w1r[l]; j++; }
            off += CC * dd;
        }
    }
    ull ip[12];
    #pragma unroll
    for (int jp = 0; jp < 12; jp++) ip[jp] = pk(img[2 * jp], img[2 * jp + 1]);
    float i24 = img[24];

    for (int i2 = i2beg; i2 < i2end; i2++) {
        const float* Mr = Ms + i2 * 28;
        ull a0 = 0ULL;
        #pragma unroll
        for (int q4 = 0; q4 < 6; q4++) {
            ulonglong2 mp = *(const ulonglong2*)(Mr + 4 * q4);
            fma2(a0, mp.x, ip[2 * q4]);
            fma2(a0, mp.y, ip[2 * q4 + 1]);
        }
        float lo, hi; upk(a0, lo, hi);
        float f = lo + hi + Mr[24] * i24;
        __nv_bfloat16 h  = __float2bfloat16(f);
        __nv_bfloat16 lw = __float2bfloat16(f - __bfloat162float(h));
        sfh[i2 * CC + c] = h;
        sfl[i2 * CC + c] = lw;
    }
    __syncthreads();

    // wide flush: 2 planes x 25 rows x 16 uint4
    size_t brow = (size_t)b * CC;
    const uint4* s4h = (const uint4*)sfh;
    const uint4* s4l = (const uint4*)sfl;
    for (int q = t; q < 800; q += 256) {
        int plane = q >= 400;
        int qq = plane ? q - 400 : q;
        int i2 = qq >> 4, k = qq & 15;
        uint4 v = plane ? s4l[qq] : s4h[qq];
        __nv_bfloat16* gp = plane ? g_fl : g_fh;
        ((uint4*)(gp + (size_t)i2 * NB * CC + brow))[k] = v;
    }
}

// ---------------- stage 2: persistent HMMA GEMM, fused 3-pass, -> g_o ----------------
// smem (1024-aligned): Bh 32K | Bl 32K | A[buf][hl] 4x32K  = 192K
#define SB_H 0
#define SB_L 32768
#define SA(buf, hl) (65536 + (buf) * 65536 + (hl) * 32768)
#define NCTA 148

__global__ void __launch_bounds__(512) out_gemm(const float* __restrict__ wc) {
    extern __shared__ char raw[];
    uint32_t sb = smem_u32(raw);
    uint32_t base = (sb + 1023) & ~1023u;
    char* cb = raw + (base - sb);

    int t = threadIdx.x, wid = t >> 5, lane = t & 31;
    int wr = wid >> 2, wcid = wid & 3;       // 4x4 warp grid, warp tile 32x32
    int cta = blockIdx.x;
    int n0 = (3200 * cta) / NCTA, n1 = (3200 * (cta + 1)) / NCTA;

    int ra = ((lane >> 3) & 1) * 8 + (lane & 7);
    int rb = ((lane >> 4) & 1) * 8 + (lane & 7);
    int rsw = lane & 7;
    int ckA = (lane >> 4) & 1, ckB = (lane >> 3) & 1;
    uint32_t arow[2], brow[2];
    #pragma unroll
    for (int mt = 0; mt < 2; mt++) arow[mt] = (uint32_t)((wr * 32 + mt * 16 + ra) * 256);
    #pragma unroll
    for (int pt = 0; pt < 2; pt++) brow[pt] = (uint32_t)((wcid * 32 + pt * 16 + rb) * 256);

    auto load_A = [&](int n, int buf) {
        int i = n / 128, bt = n % 128;
        size_t ab = ((size_t)i * NB + (size_t)bt * 128) * CC;
        const char* sH = (const char*)(g_fh + ab);
        const char* sL = (const char*)(g_fl + ab);
        for (int q = t; q < 2048; q += 512) {
            int r = q >> 4, c16 = q & 15;
            uint32_t off = r * 256 + ((c16 ^ (r & 7)) << 4);
            cpa16(base + SA(buf, 0) + off, sH + q * 16);
            cpa16(base + SA(buf, 1) + off, sL + q * 16);
        }
        CP_COMMIT();
    };

    int lcur = -1;
    load_A(n0, 0);

    for (int n = n0; n < n1; n++) {
        int buf = (n - n0) & 1;
        int i = n / 128, bt = n % 128, l = c_lidx[i];

        if (l != lcur) {
            const float* wl = wc + (size_t)l * (CC * CC);
            for (int q = t; q < CC * CC; q += 512) {
                int c = q >> 7, a = q & 127;
                float w = wl[q];
                __nv_bfloat16 h  = __float2bfloat16(w);
                __nv_bfloat16 lo = __float2bfloat16(w - __bfloat162float(h));
                uint32_t off = (uint32_t)(a * 256 + (((c >> 3) ^ (a & 7)) << 4) + (c & 7) * 2);
                *(__nv_bfloat16*)(cb + SB_H + off) = h;
                *(__nv_bfloat16*)(cb + SB_L + off) = lo;
            }
            lcur = l;
        }

        if (n + 1 < n1) load_A(n + 1, buf ^ 1);
        if (n + 1 < n1) { CP_WAIT(1); } else { CP_WAIT(0); }
        __syncthreads();

        float acc[2][4][4];
        #pragma unroll
        for (int mt = 0; mt < 2; mt++)
            #pragma unroll
            for (int nt = 0; nt < 4; nt++)
                #pragma unroll
                for (int e2 = 0; e2 < 4; e2++) acc[mt][nt][e2] = 0.f;

        uint32_t aH = base + SA(buf, 0), aL = base + SA(buf, 1);
        uint32_t bH = base + SB_H,       bL = base + SB_L;

        #pragma unroll
        for (int s = 0; s < 8; s++) {
            uint32_t swA = (uint32_t)(((2 * s + ckA) ^ rsw) << 4);
            uint32_t swB = (uint32_t)(((2 * s + ckB) ^ rsw) << 4);
            uint32_t fah[2][4], fal[2][4], fbh[2][4], fbl[2][4];
            #pragma unroll
            for (int mt = 0; mt < 2; mt++) {
                ldsm4(fah[mt], aH + arow[mt] + swA);
                ldsm4(fal[mt], aL + arow[mt] + swA);
            }
            #pragma unroll
            for (int pt = 0; pt < 2; pt++) {
                ldsm4(fbh[pt], bH + brow[pt] + swB);
                ldsm4(fbl[pt], bL + brow[pt] + swB);
            }
            #pragma unroll
            for (int mt = 0; mt < 2; mt++)
                #pragma unroll
                for (int nt = 0; nt < 4; nt++) {
                    const int pt = nt >> 1, hv = (nt & 1) * 2;
                    mma16816(acc[mt][nt], fah[mt], &fbh[pt][hv]);
                    mma16816(acc[mt][nt], fah[mt], &fbl[pt][hv]);
                    mma16816(acc[mt][nt], fal[mt], &fbh[pt][hv]);
                }
        }

        #pragma unroll
        for (int mt = 0; mt < 2; mt++) {
            int r0 = bt * 128 + wr * 32 + mt * 16 + (lane >> 2);
            float* o0 = g_o + (size_t)r0 * OUTW + i * 128;
            float* o1 = o0 + 8 * (size_t)OUTW;
            #pragma unroll
            for (int nt = 0; nt < 4; nt++) {
                int col = wcid * 32 + nt * 8 + (lane & 3) * 2;
                float2 v0 = { acc[mt][nt][0], acc[mt][nt][1] };
                float2 v1 = { acc[mt][nt][2], acc[mt][nt][3] };
                *(float2*)(o0 + col) = v0;
                *(float2*)(o1 + col) = v1;
            }
        }
        __syncthreads();
    }
}

// ---------------- stage 3: row permutation g_o[b][i*128+a] -> out[b][...] ----------------
#define RER 32
__global__ void __launch_bounds__(512) reorder_kernel(float* __restrict__ out) {
    __shared__ float buf[NLM * BUFSTRIDE];       // padded rows: bank-spread gather
    __shared__ unsigned short maps[OUTW];
    int t = threadIdx.x;
    for (int q = t; q < OUTW; q += 512) maps[q] = d_map[q];

    int r0 = blockIdx.x * RER;
    for (int r = r0; r < r0 + RER; r++) {
        __syncthreads();
        const float4* src = (const float4*)(g_o + (size_t)r * OUTW);
        for (int q = t; q < OUTW / 4; q += 512) {
            float4 v = src[q];
            int lin = 4 * q;                      // i = lin>>7, a = lin&127
            float* dst = buf + (lin >> 7) * BUFSTRIDE + (lin & 127);
            dst[0] = v.x; dst[1] = v.y; dst[2] = v.z; dst[3] = v.w;
        }
        __syncthreads();
        float4* dst = (float4*)(out + (size_t)r * OUTW);
        for (int q = t; q < OUTW / 4; q += 512) {
            float4 v;
            v.x = buf[maps[4 * q + 0]];
            v.y = buf[maps[4 * q + 1]];
            v.z = buf[maps[4 * q + 2]];
            v.w = buf[maps[4 * q + 3]];
            dst[q] = v;
        }
    }
}

// ---------------- launch ----------------
extern "C" void kernel_launch(void* const* d_in, const int* in_sizes, int n_in,
                              void* d_out, int out_size) {
    const float* feature = (const float*)d_in[0];
    const float* sh      = (const float*)d_in[1];
    const float* w1      = (const float*)d_in[2];
    const float* w2      = (const float*)d_in[3];
    const float* wc      = (const float*)d_in[4];
    float* out = (float*)d_out;

    const int OUT_SMEM = 196608 + 1024;
    cudaFuncSetAttribute(out_gemm, cudaFuncAttributeMaxDynamicSharedMemorySize, OUT_SMEM);

    init_T_kernel<<<NLM * NLM, 256>>>(w2);
    msolve_kernel<<<NB / 64, 640>>>(sh);
    feat_kernel<<<NB, 256>>>(feature, w1);
    out_gemm<<<NCTA, 512, OUT_SMEM>>>(wc);
    reorder_kernel<<<NB / RER, 512>>>(out);
}

// round 14
// speedup vs baseline: 1.0766x; 1.0766x over previous
#include <cuda_runtime.h>
#include <cuda_bf16.h>
#include <math.h>
#include <stdint.h>

#define NLM  25
#define CC   128
#define NB   16384
#define RB   16
#define RA   15
#define GRES 240
#define PI_D 3.14159265358979323846264338327950288
#define MSTRIDE 700            // 175 float4 per M row, 16B-aligned rows
#define OUTW 3200
#define BUFSTRIDE 133          // reorder smem row stride (bank-spread)
typedef unsigned long long ull;

// ---------------- device globals ----------------
__device__ float  d_T2[NLM * NLM * NLM];                 // k-major: [k][e], e=i*25+j (w2 folded)
__device__ float  d_M[(size_t)NB * MSTRIDE];             // per-b M, col = i*28+j
__device__ __nv_bfloat16 g_fh[(size_t)NLM * NB * CC];    // feat hi  [i][b][c]
__device__ __nv_bfloat16 g_fl[(size_t)NLM * NB * CC];    // feat lo
__device__ float  g_o[(size_t)NB * OUTW];                // GEMM result [b][i*128+a]
__device__ unsigned short d_map[OUTW];                   // out col -> i*BUFSTRIDE+a (padded)

__constant__ int c_lidx[NLM] = {0, 1,1,1, 2,2,2,2,2, 3,3,3,3,3,3,3, 4,4,4,4,4,4,4,4,4};

__constant__ double c_glx[8] = {
    0.09501250983763744, 0.28160355077925891, 0.45801677765722739, 0.61787624440264375,
    0.75540440835500303, 0.86563120238783174, 0.94457502307323258, 0.98940093499164993 };
__constant__ double c_glw[8] = {
    0.18945061045506850, 0.18260341504492359, 0.16915651939500254, 0.14959598881657673,
    0.12462897125553387, 0.09515851168249278, 0.06225352393864789, 0.02715245941175409 };

// ---------------- helpers ----------------
__device__ __forceinline__ ull pk(float lo, float hi) {
    ull r; asm("mov.b64 %0, {%1, %2};" : "=l"(r) : "f"(lo), "f"(hi)); return r;
}
__device__ __forceinline__ void upk(ull v, float &lo, float &hi) {
    asm("mov.b64 {%0, %1}, %2;" : "=f"(lo), "=f"(hi) : "l"(v));
}
__device__ __forceinline__ void fma2(ull &d, ull a, ull b) {
    asm("fma.rn.f32x2 %0, %1, %2, %0;" : "+l"(d) : "l"(a), "l"(b));
}
__device__ __forceinline__ uint32_t smem_u32(const void* p) {
    uint32_t a;
    asm("{ .reg .u64 t; cvta.to.shared.u64 t, %1; cvt.u32.u64 %0, t; }" : "=r"(a) : "l"(p));
    return a;
}
__device__ __forceinline__ void cpa16(uint32_t dst, const void* src) {
    asm volatile("cp.async.cg.shared.global [%0], [%1], 16;" :: "r"(dst), "l"(src) : "memory");
}
#define CP_COMMIT() asm volatile("cp.async.commit_group;" ::: "memory")
#define CP_WAIT(n)  asm volatile("cp.async.wait_group %0;" :: "n"(n) : "memory")

__device__ __forceinline__ void ldsm4(uint32_t* r, uint32_t addr) {
    asm volatile("ldmatrix.sync.aligned.m8n8.x4.shared.b16 {%0,%1,%2,%3}, [%4];"
        : "=r"(r[0]), "=r"(r[1]), "=r"(r[2]), "=r"(r[3]) : "r"(addr));
}
__device__ __forceinline__ void mma16816(float* d, const uint32_t* a, const uint32_t* b) {
    asm volatile("mma.sync.aligned.m16n8k16.row.col.f32.bf16.bf16.f32 "
        "{%0,%1,%2,%3}, {%4,%5,%6,%7}, {%8,%9}, {%0,%1,%2,%3};"
        : "+f"(d[0]), "+f"(d[1]), "+f"(d[2]), "+f"(d[3])
        : "r"(a[0]), "r"(a[1]), "r"(a[2]), "r"(a[3]), "r"(b[0]), "r"(b[1]));
}

// ---------------- init: Y + T2[k][e] + out map (single-sync reduction) ----------------
__global__ void __launch_bounds__(256) init_T_kernel(const float* __restrict__ w2) {
    __shared__ float Ys[NLM * GRES];   // 24KB
    __shared__ float redp[8 * NLM];
    int e = blockIdx.x;                // (i,j), 0..624
    int i = e / NLM, j = e % NLM;
    int t = threadIdx.x, wid = t >> 5, lane = t & 31;

    if (e == 0) {                      // build padded out-column permutation map
        for (int c = t; c < OUTW; c += 256) {
            int l = 0;
            while (c >= 128 * (l + 1) * (l + 1)) l++;
            int off = c - 128 * l * l;
            int dd = 2 * l + 1;
            int a = off / dd, mi = off - a * dd;
            d_map[c] = (unsigned short)((l * l + mi) * BUFSTRIDE + a);
        }
    }

    if (t < GRES) {
        int g = t / RA, h = t % RA;
        float xx = (float)((g < 8) ? c_glx[g] : -c_glx[g - 8]);
        float s = sqrtf(fmaxf(0.f, 1.f - xx * xx));
        float P[5][5];
        P[0][0] = 1.f;
        #pragma unroll
        for (int m = 1; m <= 4; m++) P[m][m] = -(2.f * m - 1.f) * s * P[m - 1][m - 1];
        #pragma unroll
        for (int m = 0; m <= 3; m++) P[m + 1][m] = (2.f * m + 1.f) * xx * P[m][m];
        #pragma unroll
        for (int m = 0; m <= 4; m++)
            #pragma unroll
            for (int l = m + 2; l <= 4; l++)
                P[l][m] = ((2.f * l - 1.f) * xx * P[l - 1][m] - (l + m - 1.f) * P[l - 2][m]) / (float)(l - m);
        float alpha = (float)(2.0 * PI_D * (double)h / (double)RA);
        float fact[9]; fact[0] = 1.f;
        #pragma unroll
        for (int q = 1; q < 9; q++) fact[q] = fact[q - 1] * q;
        int ii = 0;
        #pragma unroll
        for (int l = 0; l <= 4; l++)
            for (int mm = -l; mm <= l; mm++) {
                int am = mm < 0 ? -mm : mm;
                float K = sqrtf((2.f * l + 1.f) / (4.f * (float)PI_D) * fact[l - am] / fact[l + am]);
                float y;
                if (mm == 0)      y = K * P[l][0];
                else if (mm > 0)  y = 1.41421356237309515f * K * P[l][am] * cosf(am * alpha);
                else              y = 1.41421356237309515f * K * P[l][am] * sinf(am * alpha);
                Ys[ii * GRES + t] = y;
                ii++;
            }
    }
    __syncthreads();

    float wyy = 0.f;
    if (t < GRES) {
        int g = t / RA;
        float wqv = (float)(c_glw[g & 7] * (2.0 * PI_D / (double)RA));
        wyy = wqv * Ys[i * GRES + t] * Ys[j * GRES + t];
    }
    #pragma unroll
    for (int k = 0; k < NLM; k++) {
        float v = (t < GRES) ? wyy * Ys[k * GRES + t] : 0.f;
        #pragma unroll
        for (int off = 16; off; off >>= 1) v += __shfl_down_sync(0xffffffffu, v, off);
        if (lane == 0) redp[wid * NLM + k] = v;
    }
    __syncthreads();
    if (t < NLM) {
        float s2 = 0.f;
        #pragma unroll
        for (int w = 0; w < 8; w++) s2 += redp[w * NLM + t];
        d_T2[t * (NLM * NLM) + e] = s2 * w2[c_lidx[t]];
    }
}

// ---------------- stage 0: M[b][i,j] = sum_k T2[k][e]*sh[b][k] ----------------
__global__ void __launch_bounds__(640) msolve_kernel(const float* __restrict__ sh) {
    __shared__ __align__(16) ull shp[NLM * 32];   // [k][bpair]
    int t = threadIdx.x;
    int b0 = blockIdx.x * 64;

    for (int q = t; q < NLM * 32; q += 640) {
        int k = q >> 5, bp = q & 31;
        shp[q] = pk(sh[(size_t)(b0 + 2 * bp) * NLM + k], sh[(size_t)(b0 + 2 * bp + 1) * NLM + k]);
    }
    __syncthreads();

    if (t < 625) {
        ull t2p[NLM];
        #pragma unroll
        for (int k = 0; k < NLM; k++) {
            float v = d_T2[k * 625 + t];
            t2p[k] = pk(v, v);
        }
        int col = (t / 25) * 28 + t % 25;
        for (int bq = 0; bq < 16; bq++) {
            ull a0 = 0ULL, a1 = 0ULL;
            #pragma unroll
            for (int k = 0; k < NLM; k++) {
                ulonglong2 sp = *(const ulonglong2*)&shp[k * 32 + 2 * bq];
                fma2(a0, t2p[k], sp.x);
                fma2(a1, t2p[k], sp.y);
            }
            float x0, x1, y0, y1;
            upk(a0, x0, x1); upk(a1, y0, y1);
            size_t r = (size_t)(b0 + 4 * bq) * MSTRIDE + col;
            d_M[r]               = x0;
            d_M[r + MSTRIDE]     = x1;
            d_M[r + 2 * MSTRIDE] = y0;
            d_M[r + 3 * MSTRIDE] = y1;
        }
    }
}

// ---------------- stage 1: feat (bf16 hi/lo) — R11-verified 128-thread version ----------------
__global__ void __launch_bounds__(128) feat_kernel(const float* __restrict__ feature,
                                                   const float* __restrict__ w1) {
    __shared__ float fs[CC * NLM];
    __shared__ __align__(16) float Ms[MSTRIDE];
    int b = blockIdx.x, t = threadIdx.x;

    const float4* f4 = (const float4*)(feature + (size_t)b * (CC * NLM));
    for (int q = t; q < CC * NLM / 4; q += 128) ((float4*)fs)[q] = f4[q];
    const float4* m4 = (const float4*)(d_M + (size_t)b * MSTRIDE);
    for (int q = t; q < MSTRIDE / 4; q += 128) ((float4*)Ms)[q] = m4[q];
    __syncthreads();

    int c = t;
    float w1r[5];
    #pragma unroll
    for (int l = 0; l < 5; l++) w1r[l] = w1[c * 5 + l];

    float img[NLM];
    {
        int off = 0, j = 0;
        #pragma unroll
        for (int l = 0; l <= 4; l++) {
            int dd = 2 * l + 1;
            #pragma unroll
            for (int m = 0; m < dd; m++) { img[j] = fs[off + c * dd + m] * w1r[l]; j++; }
            off += CC * dd;
        }
    }
    ull ip[12];
    #pragma unroll
    for (int jp = 0; jp < 12; jp++) ip[jp] = pk(img[2 * jp], img[2 * jp + 1]);
    float i24 = img[24];

    size_t bi = (size_t)b * CC + c;
    #pragma unroll
    for (int i2 = 0; i2 < NLM; i2++) {
        const float* Mr = Ms + i2 * 28;
        ull a0 = 0ULL;
        #pragma unroll
        for (int q4 = 0; q4 < 6; q4++) {
            ulonglong2 mp = *(const ulonglong2*)(Mr + 4 * q4);
            fma2(a0, mp.x, ip[2 * q4]);
            fma2(a0, mp.y, ip[2 * q4 + 1]);
        }
        float lo, hi; upk(a0, lo, hi);
        float f = lo + hi + Mr[24] * i24;
        __nv_bfloat16 h  = __float2bfloat16(f);
        __nv_bfloat16 lw = __float2bfloat16(f - __bfloat162float(h));
        size_t idx = (size_t)i2 * NB * CC + bi;
        g_fh[idx] = h;
        g_fl[idx] = lw;
    }
}

// ---------------- stage 2: persistent HMMA GEMM, fused 3-pass, -> g_o ----------------
// smem (1024-aligned): Bh 32K | Bl 32K | A[buf][hl] 4x32K  = 192K
#define SB_H 0
#define SB_L 32768
#define SA(buf, hl) (65536 + (buf) * 65536 + (hl) * 32768)
#define NCTA 148

__global__ void __launch_bounds__(512) out_gemm(const float* __restrict__ wc) {
    extern __shared__ char raw[];
    uint32_t sb = smem_u32(raw);
    uint32_t base = (sb + 1023) & ~1023u;
    char* cb = raw + (base - sb);

    int t = threadIdx.x, wid = t >> 5, lane = t & 31;
    int wr = wid >> 2, wcid = wid & 3;       // 4x4 warp grid, warp tile 32x32
    int cta = blockIdx.x;
    int n0 = (3200 * cta) / NCTA, n1 = (3200 * (cta + 1)) / NCTA;

    int ra = ((lane >> 3) & 1) * 8 + (lane & 7);
    int rb = ((lane >> 4) & 1) * 8 + (lane & 7);
    int rsw = lane & 7;
    int ckA = (lane >> 4) & 1, ckB = (lane >> 3) & 1;
    uint32_t arow[2], brow[2];
    #pragma unroll
    for (int mt = 0; mt < 2; mt++) arow[mt] = (uint32_t)((wr * 32 + mt * 16 + ra) * 256);
    #pragma unroll
    for (int pt = 0; pt < 2; pt++) brow[pt] = (uint32_t)((wcid * 32 + pt * 16 + rb) * 256);

    auto load_A = [&](int n, int buf) {
        int i = n / 128, bt = n % 128;
        size_t ab = ((size_t)i * NB + (size_t)bt * 128) * CC;
        const char* sH = (const char*)(g_fh + ab);
        const char* sL = (const char*)(g_fl + ab);
        for (int q = t; q < 2048; q += 512) {
            int r = q >> 4, c16 = q & 15;
            uint32_t off = r * 256 + ((c16 ^ (r & 7)) << 4);
            cpa16(base + SA(buf, 0) + off, sH + q * 16);
            cpa16(base + SA(buf, 1) + off, sL + q * 16);
        }
        CP_COMMIT();
    };

    int lcur = -1;
    load_A(n0, 0);

    for (int n = n0; n < n1; n++) {
        int buf = (n - n0) & 1;
        int i = n / 128, bt = n % 128, l = c_lidx[i];

        if (l != lcur) {
            const float* wl = wc + (size_t)l * (CC * CC);
            for (int q = t; q < CC * CC; q += 512) {
                int c = q >> 7, a = q & 127;
                float w = wl[q];
                __nv_bfloat16 h  = __float2bfloat16(w);
                __nv_bfloat16 lo = __float2bfloat16(w - __bfloat162float(h));
                uint32_t off = (uint32_t)(a * 256 + (((c >> 3) ^ (a & 7)) << 4) + (c & 7) * 2);
                *(__nv_bfloat16*)(cb + SB_H + off) = h;
                *(__nv_bfloat16*)(cb + SB_L + off) = lo;
            }
            lcur = l;
        }

        if (n + 1 < n1) load_A(n + 1, buf ^ 1);
        if (n + 1 < n1) { CP_WAIT(1); } else { CP_WAIT(0); }
        __syncthreads();

        float acc[2][4][4];
        #pragma unroll
        for (int mt = 0; mt < 2; mt++)
            #pragma unroll
            for (int nt = 0; nt < 4; nt++)
                #pragma unroll
                for (int e2 = 0; e2 < 4; e2++) acc[mt][nt][e2] = 0.f;

        uint32_t aH = base + SA(buf, 0), aL = base + SA(buf, 1);
        uint32_t bH = base + SB_H,       bL = base + SB_L;

        #pragma unroll
        for (int s = 0; s < 8; s++) {
            uint32_t swA = (uint32_t)(((2 * s + ckA) ^ rsw) << 4);
            uint32_t swB = (uint32_t)(((2 * s + ckB) ^ rsw) << 4);
            uint32_t fah[2][4], fal[2][4], fbh[2][4], fbl[2][4];
            #pragma unroll
            for (int mt = 0; mt < 2; mt++) {
                ldsm4(fah[mt], aH + arow[mt] + swA);
                ldsm4(fal[mt], aL + arow[mt] + swA);
            }
            #pragma unroll
            for (int pt = 0; pt < 2; pt++) {
                ldsm4(fbh[pt], bH + brow[pt] + swB);
                ldsm4(fbl[pt], bL + brow[pt] + swB);
            }
            #pragma unroll
            for (int mt = 0; mt < 2; mt++)
                #pragma unroll
                for (int nt = 0; nt < 4; nt++) {
                    const int pt = nt >> 1, hv = (nt & 1) * 2;
                    mma16816(acc[mt][nt], fah[mt], &fbh[pt][hv]);
                    mma16816(acc[mt][nt], fah[mt], &fbl[pt][hv]);
                    mma16816(acc[mt][nt], fal[mt], &fbh[pt][hv]);
                }
        }

        #pragma unroll
        for (int mt = 0; mt < 2; mt++) {
            int r0 = bt * 128 + wr * 32 + mt * 16 + (lane >> 2);
            float* o0 = g_o + (size_t)r0 * OUTW + i * 128;
            float* o1 = o0 + 8 * (size_t)OUTW;
            #pragma unroll
            for (int nt = 0; nt < 4; nt++) {
                int col = wcid * 32 + nt * 8 + (lane & 3) * 2;
                float2 v0 = { acc[mt][nt][0], acc[mt][nt][1] };
                float2 v1 = { acc[mt][nt][2], acc[mt][nt][3] };
                *(float2*)(o0 + col) = v0;
                *(float2*)(o1 + col) = v1;
            }
        }
        __syncthreads();
    }
}

// ---------------- stage 3: row permutation g_o[b][i*128+a] -> out[b][...] ----------------
#define RER 32
__global__ void __launch_bounds__(512) reorder_kernel(float* __restrict__ out) {
    __shared__ float buf[NLM * BUFSTRIDE];       // padded rows: bank-spread gather
    __shared__ unsigned short maps[OUTW];
    int t = threadIdx.x;
    for (int q = t; q < OUTW; q += 512) maps[q] = d_map[q];

    int r0 = blockIdx.x * RER;
    for (int r = r0; r < r0 + RER; r++) {
        __syncthreads();
        const float4* src = (const float4*)(g_o + (size_t)r * OUTW);
        for (int q = t; q < OUTW / 4; q += 512) {
            float4 v = src[q];
            int lin = 4 * q;                      // i = lin>>7, a = lin&127
            float* dst = buf + (lin >> 7) * BUFSTRIDE + (lin & 127);
            dst[0] = v.x; dst[1] = v.y; dst[2] = v.z; dst[3] = v.w;
        }
        __syncthreads();
        float4* dst = (float4*)(out + (size_t)r * OUTW);
        for (int q = t; q < OUTW / 4; q += 512) {
            float4 v;
            v.x = buf[maps[4 * q + 0]];
            v.y = buf[maps[4 * q + 1]];
            v.z = buf[maps[4 * q + 2]];
            v.w = buf[maps[4 * q + 3]];
            dst[q] = v;
        }
    }
}

// ---------------- launch ----------------
extern "C" void kernel_launch(void* const* d_in, const int* in_sizes, int n_in,
                              void* d_out, int out_size) {
    const float* feature = (const float*)d_in[0];
    const float* sh      = (const float*)d_in[1];
    const float* w1      = (const float*)d_in[2];
    const float* w2      = (const float*)d_in[3];
    const float* wc      = (const float*)d_in[4];
    float* out = (float*)d_out;

    const int OUT_SMEM = 196608 + 1024;
    cudaFuncSetAttribute(out_gemm, cudaFuncAttributeMaxDynamicSharedMemorySize, OUT_SMEM);

    init_T_kernel<<<NLM * NLM, 256>>>(w2);
    msolve_kernel<<<NB / 64, 640>>>(sh);
    feat_kernel<<<NB, 128>>>(feature, w1);
    out_gemm<<<NCTA, 512, OUT_SMEM>>>(wc);
    reorder_kernel<<<NB / RER, 512>>>(out);
}

// round 15
// speedup vs baseline: 1.1174x; 1.0379x over previous
#include <cuda_runtime.h>
#include <cuda_bf16.h>
#include <math.h>
#include <stdint.h>

#define NLM  25
#define CC   128
#define NB   16384
#define RB   16
#define RA   15
#define GRES 240
#define PI_D 3.14159265358979323846264338327950288
#define MSTRIDE 700            // 175 float4 per M row, 16B-aligned rows
#define OUTW 3200
#define BUFSTRIDE 132          // reorder smem row stride: 16B-aligned (528B), bank step 4
typedef unsigned long long ull;

// ---------------- device globals ----------------
__device__ float  d_T2[NLM * NLM * NLM];                 // k-major: [k][e], e=i*25+j (w2 folded)
__device__ float  d_M[(size_t)NB * MSTRIDE];             // per-b M, col = i*28+j
__device__ __nv_bfloat16 g_fh[(size_t)NLM * NB * CC];    // feat hi  [i][b][c]
__device__ __nv_bfloat16 g_fl[(size_t)NLM * NB * CC];    // feat lo
__device__ float  g_o[(size_t)NB * OUTW];                // GEMM result [b][i*128+a]
__device__ unsigned short d_map[OUTW];                   // out col -> i*BUFSTRIDE+a (padded)

__constant__ int c_lidx[NLM] = {0, 1,1,1, 2,2,2,2,2, 3,3,3,3,3,3,3, 4,4,4,4,4,4,4,4,4};

__constant__ double c_glx[8] = {
    0.09501250983763744, 0.28160355077925891, 0.45801677765722739, 0.61787624440264375,
    0.75540440835500303, 0.86563120238783174, 0.94457502307323258, 0.98940093499164993 };
__constant__ double c_glw[8] = {
    0.18945061045506850, 0.18260341504492359, 0.16915651939500254, 0.14959598881657673,
    0.12462897125553387, 0.09515851168249278, 0.06225352393864789, 0.02715245941175409 };

// ---------------- helpers ----------------
__device__ __forceinline__ ull pk(float lo, float hi) {
    ull r; asm("mov.b64 %0, {%1, %2};" : "=l"(r) : "f"(lo), "f"(hi)); return r;
}
__device__ __forceinline__ void upk(ull v, float &lo, float &hi) {
    asm("mov.b64 {%0, %1}, %2;" : "=f"(lo), "=f"(hi) : "l"(v));
}
__device__ __forceinline__ void fma2(ull &d, ull a, ull b) {
    asm("fma.rn.f32x2 %0, %1, %2, %0;" : "+l"(d) : "l"(a), "l"(b));
}
__device__ __forceinline__ uint32_t smem_u32(const void* p) {
    uint32_t a;
    asm("{ .reg .u64 t; cvta.to.shared.u64 t, %1; cvt.u32.u64 %0, t; }" : "=r"(a) : "l"(p));
    return a;
}
__device__ __forceinline__ void cpa16(uint32_t dst, const void* src) {
    asm volatile("cp.async.cg.shared.global [%0], [%1], 16;" :: "r"(dst), "l"(src) : "memory");
}
#define CP_COMMIT() asm volatile("cp.async.commit_group;" ::: "memory")
#define CP_WAIT(n)  asm volatile("cp.async.wait_group %0;" :: "n"(n) : "memory")

__device__ __forceinline__ void ldsm4(uint32_t* r, uint32_t addr) {
    asm volatile("ldmatrix.sync.aligned.m8n8.x4.shared.b16 {%0,%1,%2,%3}, [%4];"
        : "=r"(r[0]), "=r"(r[1]), "=r"(r[2]), "=r"(r[3]) : "r"(addr));
}
__device__ __forceinline__ void mma16816(float* d, const uint32_t* a, const uint32_t* b) {
    asm volatile("mma.sync.aligned.m16n8k16.row.col.f32.bf16.bf16.f32 "
        "{%0,%1,%2,%3}, {%4,%5,%6,%7}, {%8,%9}, {%0,%1,%2,%3};"
        : "+f"(d[0]), "+f"(d[1]), "+f"(d[2]), "+f"(d[3])
        : "r"(a[0]), "r"(a[1]), "r"(a[2]), "r"(a[3]), "r"(b[0]), "r"(b[1]));
}

// ---------------- init: Y + T2[k][e] + out map (single-sync reduction) ----------------
__global__ void __launch_bounds__(256) init_T_kernel(const float* __restrict__ w2) {
    __shared__ float Ys[NLM * GRES];   // 24KB
    __shared__ float redp[8 * NLM];
    int e = blockIdx.x;                // (i,j), 0..624
    int i = e / NLM, j = e % NLM;
    int t = threadIdx.x, wid = t >> 5, lane = t & 31;

    if (e == 0) {                      // build padded out-column permutation map
        for (int c = t; c < OUTW; c += 256) {
            int l = 0;
            while (c >= 128 * (l + 1) * (l + 1)) l++;
            int off = c - 128 * l * l;
            int dd = 2 * l + 1;
            int a = off / dd, mi = off - a * dd;
            d_map[c] = (unsigned short)((l * l + mi) * BUFSTRIDE + a);
        }
    }

    if (t < GRES) {
        int g = t / RA, h = t % RA;
        float xx = (float)((g < 8) ? c_glx[g] : -c_glx[g - 8]);
        float s = sqrtf(fmaxf(0.f, 1.f - xx * xx));
        float P[5][5];
        P[0][0] = 1.f;
        #pragma unroll
        for (int m = 1; m <= 4; m++) P[m][m] = -(2.f * m - 1.f) * s * P[m - 1][m - 1];
        #pragma unroll
        for (int m = 0; m <= 3; m++) P[m + 1][m] = (2.f * m + 1.f) * xx * P[m][m];
        #pragma unroll
        for (int m = 0; m <= 4; m++)
            #pragma unroll
            for (int l = m + 2; l <= 4; l++)
                P[l][m] = ((2.f * l - 1.f) * xx * P[l - 1][m] - (l + m - 1.f) * P[l - 2][m]) / (float)(l - m);
        float alpha = (float)(2.0 * PI_D * (double)h / (double)RA);
        float fact[9]; fact[0] = 1.f;
        #pragma unroll
        for (int q = 1; q < 9; q++) fact[q] = fact[q - 1] * q;
        int ii = 0;
        #pragma unroll
        for (int l = 0; l <= 4; l++)
            for (int mm = -l; mm <= l; mm++) {
                int am = mm < 0 ? -mm : mm;
                float K = sqrtf((2.f * l + 1.f) / (4.f * (float)PI_D) * fact[l - am] / fact[l + am]);
                float y;
                if (mm == 0)      y = K * P[l][0];
                else if (mm > 0)  y = 1.41421356237309515f * K * P[l][am] * cosf(am * alpha);
                else              y = 1.41421356237309515f * K * P[l][am] * sinf(am * alpha);
                Ys[ii * GRES + t] = y;
                ii++;
            }
    }
    __syncthreads();

    float wyy = 0.f;
    if (t < GRES) {
        int g = t / RA;
        float wqv = (float)(c_glw[g & 7] * (2.0 * PI_D / (double)RA));
        wyy = wqv * Ys[i * GRES + t] * Ys[j * GRES + t];
    }
    #pragma unroll
    for (int k = 0; k < NLM; k++) {
        float v = (t < GRES) ? wyy * Ys[k * GRES + t] : 0.f;
        #pragma unroll
        for (int off = 16; off; off >>= 1) v += __shfl_down_sync(0xffffffffu, v, off);
        if (lane == 0) redp[wid * NLM + k] = v;
    }
    __syncthreads();
    if (t < NLM) {
        float s2 = 0.f;
        #pragma unroll
        for (int w = 0; w < 8; w++) s2 += redp[w * NLM + t];
        d_T2[t * (NLM * NLM) + e] = s2 * w2[c_lidx[t]];
    }
}

// ---------------- stage 0: M[b][i,j] = sum_k T2[k][e]*sh[b][k] ----------------
__global__ void __launch_bounds__(640) msolve_kernel(const float* __restrict__ sh) {
    __shared__ __align__(16) ull shp[NLM * 32];   // [k][bpair]
    int t = threadIdx.x;
    int b0 = blockIdx.x * 64;

    for (int q = t; q < NLM * 32; q += 640) {
        int k = q >> 5, bp = q & 31;
        shp[q] = pk(sh[(size_t)(b0 + 2 * bp) * NLM + k], sh[(size_t)(b0 + 2 * bp + 1) * NLM + k]);
    }
    __syncthreads();

    if (t < 625) {
        ull t2p[NLM];
        #pragma unroll
        for (int k = 0; k < NLM; k++) {
            float v = d_T2[k * 625 + t];
            t2p[k] = pk(v, v);
        }
        int col = (t / 25) * 28 + t % 25;
        for (int bq = 0; bq < 16; bq++) {
            ull a0 = 0ULL, a1 = 0ULL;
            #pragma unroll
            for (int k = 0; k < NLM; k++) {
                ulonglong2 sp = *(const ulonglong2*)&shp[k * 32 + 2 * bq];
                fma2(a0, t2p[k], sp.x);
                fma2(a1, t2p[k], sp.y);
            }
            float x0, x1, y0, y1;
            upk(a0, x0, x1); upk(a1, y0, y1);
            size_t r = (size_t)(b0 + 4 * bq) * MSTRIDE + col;
            d_M[r]               = x0;
            d_M[r + MSTRIDE]     = x1;
            d_M[r + 2 * MSTRIDE] = y0;
            d_M[r + 3 * MSTRIDE] = y1;
        }
    }
}

// ---------------- stage 1: feat (bf16 hi/lo), 2 b-rows/CTA, paired channels ----------------
__global__ void __launch_bounds__(128) feat_kernel(const float* __restrict__ feature,
                                                   const float* __restrict__ w1) {
    __shared__ float fs[2][CC * NLM];                 // 25.6 KB
    __shared__ __align__(16) float Ms[2][MSTRIDE];    // 5.6 KB
    int b0 = blockIdx.x * 2, t = threadIdx.x;

    const float4* f4 = (const float4*)(feature + (size_t)b0 * (CC * NLM));
    for (int q = t; q < 2 * CC * NLM / 4; q += 128) ((float4*)fs)[q] = f4[q];
    const float4* m4 = (const float4*)(d_M + (size_t)b0 * MSTRIDE);
    for (int q = t; q < 2 * MSTRIDE / 4; q += 128) ((float4*)Ms)[q] = m4[q];
    __syncthreads();

    int bb = t >> 6;                   // which of the 2 b-rows
    int u  = t & 63;
    int c0 = 2 * u, c1 = 2 * u + 1;    // adjacent channels -> packed STG.32
    const float* fsb = fs[bb];
    const float* Msb = Ms[bb];

    float w1a[5], w1b[5];
    #pragma unroll
    for (int l = 0; l < 5; l++) { w1a[l] = w1[c0 * 5 + l]; w1b[l] = w1[c1 * 5 + l]; }

    float img0[NLM], img1[NLM];
    {
        int off = 0, j = 0;
        #pragma unroll
        for (int l = 0; l <= 4; l++) {
            int dd = 2 * l + 1;
            #pragma unroll
            for (int m = 0; m < dd; m++) {
                img0[j] = fsb[off + c0 * dd + m] * w1a[l];
                img1[j] = fsb[off + c1 * dd + m] * w1b[l];
                j++;
            }
            off += CC * dd;
        }
    }
    ull ip0[12], ip1[12];
    #pragma unroll
    for (int jp = 0; jp < 12; jp++) {
        ip0[jp] = pk(img0[2 * jp], img0[2 * jp + 1]);
        ip1[jp] = pk(img1[2 * jp], img1[2 * jp + 1]);
    }
    float i24a = img0[24], i24b = img1[24];

    size_t bi = (size_t)(b0 + bb) * CC + c0;   // even offset -> 4B-aligned bf16 pair
    #pragma unroll
    for (int i2 = 0; i2 < NLM; i2++) {
        const float* Mr = Msb + i2 * 28;
        ull a0 = 0ULL, a1 = 0ULL;
        #pragma unroll
        for (int q4 = 0; q4 < 6; q4++) {
            ulonglong2 mp = *(const ulonglong2*)(Mr + 4 * q4);
            fma2(a0, mp.x, ip0[2 * q4]);
            fma2(a0, mp.y, ip0[2 * q4 + 1]);
            fma2(a1, mp.x, ip1[2 * q4]);
            fma2(a1, mp.y, ip1[2 * q4 + 1]);
        }
        float l0, h0, l1, h1;
        upk(a0, l0, h0); upk(a1, l1, h1);
        float m24 = Mr[24];
        float f0 = l0 + h0 + m24 * i24a;
        float f1 = l1 + h1 + m24 * i24b;
        __nv_bfloat16 hh0 = __float2bfloat16(f0);
        __nv_bfloat16 hh1 = __float2bfloat16(f1);
        __nv_bfloat16 lw0 = __float2bfloat16(f0 - __bfloat162float(hh0));
        __nv_bfloat16 lw1 = __float2bfloat16(f1 - __bfloat162float(hh1));
        uint32_t hp = (uint32_t)__bfloat16_as_ushort(hh0) | ((uint32_t)__bfloat16_as_ushort(hh1) << 16);
        uint32_t lp = (uint32_t)__bfloat16_as_ushort(lw0) | ((uint32_t)__bfloat16_as_ushort(lw1) << 16);
        size_t idx = (size_t)i2 * NB * CC + bi;
        *(uint32_t*)(g_fh + idx) = hp;
        *(uint32_t*)(g_fl + idx) = lp;
    }
}

// ---------------- stage 2: persistent HMMA GEMM, fused 3-pass, -> g_o (R12-verified) ----------------
// smem (1024-aligned): Bh 32K | Bl 32K | A[buf][hl] 4x32K  = 192K
#define SB_H 0
#define SB_L 32768
#define SA(buf, hl) (65536 + (buf) * 65536 + (hl) * 32768)
#define NCTA 148

__global__ void __launch_bounds__(512) out_gemm(const float* __restrict__ wc) {
    extern __shared__ char raw[];
    uint32_t sb = smem_u32(raw);
    uint32_t base = (sb + 1023) & ~1023u;
    char* cb = raw + (base - sb);

    int t = threadIdx.x, wid = t >> 5, lane = t & 31;
    int wr = wid >> 2, wcid = wid & 3;       // 4x4 warp grid, warp tile 32x32
    int cta = blockIdx.x;
    int n0 = (3200 * cta) / NCTA, n1 = (3200 * (cta + 1)) / NCTA;

    int ra = ((lane >> 3) & 1) * 8 + (lane & 7);
    int rb = ((lane >> 4) & 1) * 8 + (lane & 7);
    int rsw = lane & 7;
    int ckA = (lane >> 4) & 1, ckB = (lane >> 3) & 1;
    uint32_t arow[2], brow[2];
    #pragma unroll
    for (int mt = 0; mt < 2; mt++) arow[mt] = (uint32_t)((wr * 32 + mt * 16 + ra) * 256);
    #pragma unroll
    for (int pt = 0; pt < 2; pt++) brow[pt] = (uint32_t)((wcid * 32 + pt * 16 + rb) * 256);

    auto load_A = [&](int n, int buf) {
        int i = n / 128, bt = n % 128;
        size_t ab = ((size_t)i * NB + (size_t)bt * 128) * CC;
        const char* sH = (const char*)(g_fh + ab);
        const char* sL = (const char*)(g_fl + ab);
        for (int q = t; q < 2048; q += 512) {
            int r = q >> 4, c16 = q & 15;
            uint32_t off = r * 256 + ((c16 ^ (r & 7)) << 4);
            cpa16(base + SA(buf, 0) + off, sH + q * 16);
            cpa16(base + SA(buf, 1) + off, sL + q * 16);
        }
        CP_COMMIT();
    };

    int lcur = -1;
    load_A(n0, 0);

    for (int n = n0; n < n1; n++) {
        int buf = (n - n0) & 1;
        int i = n / 128, bt = n % 128, l = c_lidx[i];

        if (l != lcur) {
            const float* wl = wc + (size_t)l * (CC * CC);
            for (int q = t; q < CC * CC; q += 512) {
                int c = q >> 7, a = q & 127;
                float w = wl[q];
                __nv_bfloat16 h  = __float2bfloat16(w);
                __nv_bfloat16 lo = __float2bfloat16(w - __bfloat162float(h));
                uint32_t off = (uint32_t)(a * 256 + (((c >> 3) ^ (a & 7)) << 4) + (c & 7) * 2);
                *(__nv_bfloat16*)(cb + SB_H + off) = h;
                *(__nv_bfloat16*)(cb + SB_L + off) = lo;
            }
            lcur = l;
        }

        if (n + 1 < n1) load_A(n + 1, buf ^ 1);
        if (n + 1 < n1) { CP_WAIT(1); } else { CP_WAIT(0); }
        __syncthreads();

        float acc[2][4][4];
        #pragma unroll
        for (int mt = 0; mt < 2; mt++)
            #pragma unroll
            for (int nt = 0; nt < 4; nt++)
                #pragma unroll
                for (int e2 = 0; e2 < 4; e2++) acc[mt][nt][e2] = 0.f;

        uint32_t aH = base + SA(buf, 0), aL = base + SA(buf, 1);
        uint32_t bH = base + SB_H,       bL = base + SB_L;

        #pragma unroll
        for (int s = 0; s < 8; s++) {
            uint32_t swA = (uint32_t)(((2 * s + ckA) ^ rsw) << 4);
            uint32_t swB = (uint32_t)(((2 * s + ckB) ^ rsw) << 4);
            uint32_t fah[2][4], fal[2][4], fbh[2][4], fbl[2][4];
            #pragma unroll
            for (int mt = 0; mt < 2; mt++) {
                ldsm4(fah[mt], aH + arow[mt] + swA);
                ldsm4(fal[mt], aL + arow[mt] + swA);
            }
            #pragma unroll
            for (int pt = 0; pt < 2; pt++) {
                ldsm4(fbh[pt], bH + brow[pt] + swB);
                ldsm4(fbl[pt], bL + brow[pt] + swB);
            }
            #pragma unroll
            for (int mt = 0; mt < 2; mt++)
                #pragma unroll
                for (int nt = 0; nt < 4; nt++) {
                    const int pt = nt >> 1, hv = (nt & 1) * 2;
                    mma16816(acc[mt][nt], fah[mt], &fbh[pt][hv]);
                    mma16816(acc[mt][nt], fah[mt], &fbl[pt][hv]);
                    mma16816(acc[mt][nt], fal[mt], &fbh[pt][hv]);
                }
        }

        #pragma unroll
        for (int mt = 0; mt < 2; mt++) {
            int r0 = bt * 128 + wr * 32 + mt * 16 + (lane >> 2);
            float* o0 = g_o + (size_t)r0 * OUTW + i * 128;
            float* o1 = o0 + 8 * (size_t)OUTW;
            #pragma unroll
            for (int nt = 0; nt < 4; nt++) {
                int col = wcid * 32 + nt * 8 + (lane & 3) * 2;
                float2 v0 = { acc[mt][nt][0], acc[mt][nt][1] };
                float2 v1 = { acc[mt][nt][2], acc[mt][nt][3] };
                *(float2*)(o0 + col) = v0;
                *(float2*)(o1 + col) = v1;
            }
        }
        __syncthreads();
    }
}

// ---------------- stage 3: row permutation, cp.async double-buffered ----------------
#define RER 8
__global__ void __launch_bounds__(256) reorder_kernel(float* __restrict__ out) {
    __shared__ __align__(16) float buf[2][NLM * BUFSTRIDE];   // 2 x 13.2 KB
    __shared__ unsigned short maps[OUTW];
    int t = threadIdx.x;
    for (int q = t; q < OUTW; q += 256) maps[q] = d_map[q];

    uint32_t sbuf[2] = { smem_u32(&buf[0][0]), smem_u32(&buf[1][0]) };

    auto load_row = [&](int r, int s) {
        const char* src = (const char*)(g_o + (size_t)r * OUTW);
        for (int q = t; q < 800; q += 256) {
            int i = q >> 5, k = q & 31;                 // 32 x 16B chunks per i-row
            cpa16(sbuf[s] + (uint32_t)(i * BUFSTRIDE * 4 + k * 16),
                  src + (size_t)(i * 128 + k * 4) * 4);
        }
        CP_COMMIT();
    };

    int r0 = blockIdx.x * RER;
    load_row(r0, 0);
    for (int k2 = 0; k2 < RER; k2++) {
        int r = r0 + k2;
        if (k2 + 1 < RER) load_row(r + 1, (k2 + 1) & 1);
        if (k2 + 1 < RER) { CP_WAIT(1); } else { CP_WAIT(0); }
        __syncthreads();                                   // row r resident, prior gather done
        const float* bufc = buf[k2 & 1];
        float4* dst = (float4*)(out + (size_t)r * OUTW);
        for (int q = t; q < 800; q += 256) {
            float4 v;
            v.x = bufc[maps[4 * q + 0]];
            v.y = bufc[maps[4 * q + 1]];
            v.z = bufc[maps[4 * q + 2]];
            v.w = bufc[maps[4 * q + 3]];
            dst[q] = v;
        }
        __syncthreads();                                   // protect buf slot before next prefetch
    }
}

// ---------------- launch ----------------
extern "C" void kernel_launch(void* const* d_in, const int* in_sizes, int n_in,
                              void* d_out, int out_size) {
    const float* feature = (const float*)d_in[0];
    const float* sh      = (const float*)d_in[1];
    const float* w1      = (const float*)d_in[2];
    const float* w2      = (const float*)d_in[3];
    const float* wc      = (const float*)d_in[4];
    float* out = (float*)d_out;

    const int OUT_SMEM = 196608 + 1024;
    cudaFuncSetAttribute(out_gemm, cudaFuncAttributeMaxDynamicSharedMemorySize, OUT_SMEM);

    init_T_kernel<<<NLM * NLM, 256>>>(w2);
    msolve_kernel<<<NB / 64, 640>>>(sh);
    feat_kernel<<<NB / 2, 128>>>(feature, w1);
    out_gemm<<<NCTA, 512, OUT_SMEM>>>(wc);
    reorder_kernel<<<NB / RER, 256>>>(out);
}